// round 1
// baseline (speedup 1.0000x reference)
#include <cuda_runtime.h>

// LIF constants
#define DT            0.001f
#define TAU_MEM_INV   100.0f
#define TAU_SYN_INV   200.0f
#define V_TH          1.0f
// derived:
//   i' = syn * (1 - DT*TAU_SYN_INV) + in   = syn * 0.8 + in
//   v' = v + DT*TAU_MEM_INV*((0 - v) + i') = v * 0.9 + 0.1 * i'
#define SYN_K  (1.0f - DT * TAU_SYN_INV)   // 0.8
#define MEM_K  (1.0f - DT * TAU_MEM_INV)   // 0.9
#define IN_K   (DT * TAU_MEM_INV)          // 0.1

#define BB 16
#define CC 64
#define HH 256
#define WW 256
#define OH (HH / 2)
#define OW (WW / 2)

// Each thread: 2 adjacent output pixels along W (one float2 store),
// reading a 2-row x 4-col patch from each of the 3 input arrays (6x float4 loads).
__global__ __launch_bounds__(256) void lif_maxpool_kernel(
    const float* __restrict__ in_sig,
    const float* __restrict__ mem,
    const float* __restrict__ syn,
    float* __restrict__ out)
{
    const int tid = blockIdx.x * blockDim.x + threadIdx.x;
    // total threads = (B*C*OH*OW)/2 = 8388608
    const int ow2 = tid & (OW / 2 - 1);            // which float2 along output W (0..63)
    const int oh  = (tid >> 6) & (OH - 1);         // output row (0..127)
    const int nc  = tid >> 13;                     // fused b*C+c plane (0..1023)

    const long long in_base = (long long)nc * (HH * WW) + (long long)(2 * oh) * WW + ow2 * 4;

    const float4 i0 = *(const float4*)(in_sig + in_base);
    const float4 i1 = *(const float4*)(in_sig + in_base + WW);
    const float4 v0 = *(const float4*)(mem    + in_base);
    const float4 v1 = *(const float4*)(mem    + in_base + WW);
    const float4 s0 = *(const float4*)(syn    + in_base);
    const float4 s1 = *(const float4*)(syn    + in_base + WW);

    // v' for all 8 pixels
    // v' = MEM_K*v + IN_K*(SYN_K*syn + in)
    float v00 = fmaf(MEM_K, v0.x, IN_K * fmaf(SYN_K, s0.x, i0.x));
    float v01 = fmaf(MEM_K, v0.y, IN_K * fmaf(SYN_K, s0.y, i0.y));
    float v02 = fmaf(MEM_K, v0.z, IN_K * fmaf(SYN_K, s0.z, i0.z));
    float v03 = fmaf(MEM_K, v0.w, IN_K * fmaf(SYN_K, s0.w, i0.w));
    float v10 = fmaf(MEM_K, v1.x, IN_K * fmaf(SYN_K, s1.x, i1.x));
    float v11 = fmaf(MEM_K, v1.y, IN_K * fmaf(SYN_K, s1.y, i1.y));
    float v12 = fmaf(MEM_K, v1.z, IN_K * fmaf(SYN_K, s1.z, i1.z));
    float v13 = fmaf(MEM_K, v1.w, IN_K * fmaf(SYN_K, s1.w, i1.w));

    // spike = (v' >= 1.0) ? 1 : 0; pool = max over 2x2 window
    // max of spikes == any(v' >= V_TH) ? 1 : 0
    float p0 = (fmaxf(fmaxf(v00, v01), fmaxf(v10, v11)) >= V_TH) ? 1.0f : 0.0f;
    float p1 = (fmaxf(fmaxf(v02, v03), fmaxf(v12, v13)) >= V_TH) ? 1.0f : 0.0f;

    const long long out_base = (long long)nc * (OH * OW) + (long long)oh * OW + ow2 * 2;
    *(float2*)(out + out_base) = make_float2(p0, p1);
}

extern "C" void kernel_launch(void* const* d_in, const int* in_sizes, int n_in,
                              void* d_out, int out_size)
{
    const float* in_sig = (const float*)d_in[0];
    const float* mem    = (const float*)d_in[1];
    const float* syn    = (const float*)d_in[2];
    float* out = (float*)d_out;

    const int total_threads = (BB * CC * OH * OW) / 2;  // 8388608
    const int block = 256;
    const int grid = total_threads / block;             // 32768
    lif_maxpool_kernel<<<grid, block>>>(in_sig, mem, syn, out);
}